// round 4
// baseline (speedup 1.0000x reference)
#include <cuda_runtime.h>
#include <mma.h>
#include <cstdint>

using namespace nvcuda;

// Problem dims
#define TT   256
#define BB   32
#define NN   16
#define FF   128
#define HH   256
#define BNX  (BB*NN)        // 512 sequences
#define KX   FF             // 128 (x part of K)
#define KTOT (FF+HH)        // 384 (x | h); bias ones-col at 384
#define KEND (KTOT+8)       // 392: GEMM k upper bound (covers bias col)
#define KPAD 396            // row stride in floats (396 % 32 == 12 -> fewer LDS bank conflicts)

// Tiling
#define SEQ_TILE 32
#define J_TILE   32
#define G_SEQ (BNX/SEQ_TILE)   // 16 seq-chunks
#define G_J   (HH/J_TILE)      // 8 j-chunks
#define NCTA  (G_SEQ*G_J)      // 128 CTAs (1 per SM -> co-resident on 148 SMs)
#define NTHREADS 128

// smem layout (floats)
#define OFF_A 0
#define SZ_A  (SEQ_TILE*KPAD)          // 12672
#define OFF_W (OFF_A + SZ_A)
#define SZ_W  (3*J_TILE*KPAD)          // 38016
#define OFF_C (OFF_W + SZ_W)
#define CLD   36
#define SZ_C  (4*SEQ_TILE*CLD)         // 4608
#define OFF_H (OFF_C + SZ_C)
#define SZ_H  (SEQ_TILE*CLD)           // 1152 (exact fp32 masked-h slice)
#define OFF_BN (OFF_H + SZ_H)          // 32 floats
#define OFF_DM (OFF_BN + J_TILE)       // 32 floats
#define SMEM_FLOATS (OFF_DM + SEQ_TILE)
#define SMEM_BYTES  (SMEM_FLOATS*4)    // 226,048 B < 232,448 B dynamic-smem cap

// Cross-CTA step flags (per seq-chunk group of 8 CTAs)
__device__ int g_flags[G_SEQ][G_J];

__global__ void reset_flags_kernel() {
    int i = threadIdx.x;
    if (i < NCTA) ((int*)g_flags)[i] = 0;
}

__device__ __forceinline__ float sigf(float v) { return 1.0f / (1.0f + __expf(-v)); }

// Guaranteed-reload L2 poll / L2 publish (avoid ATOMG RMW serialization)
__device__ __forceinline__ int ld_flag(const int* p) {
    int v; asm volatile("ld.global.cg.b32 %0, [%1];" : "=r"(v) : "l"(p) : "memory"); return v;
}
__device__ __forceinline__ void st_flag(int* p, int v) {
    asm volatile("st.global.cg.b32 [%0], %1;" :: "l"(p), "r"(v) : "memory");
}

typedef wmma::fragment<wmma::matrix_a, 16,16,8, wmma::precision::tf32, wmma::row_major> FragA;
typedef wmma::fragment<wmma::matrix_b, 16,16,8, wmma::precision::tf32, wmma::col_major> FragB;
typedef wmma::fragment<wmma::accumulator, 16,16,8, float> FragC;

__global__ void __launch_bounds__(NTHREADS, 1)
slotgru_persistent_kernel(const float* __restrict__ x,
                          const int*   __restrict__ dones,
                          const float* __restrict__ h0,
                          const float* __restrict__ W_ih,
                          const float* __restrict__ W_hh,
                          const float* __restrict__ b_ih,
                          const float* __restrict__ b_hh,
                          float* __restrict__ out)
{
    extern __shared__ float sm[];
    float* As  = sm + OFF_A;   // [32][396] A tile: [x_t | masked h | 1 | 0..] (tf32)
    float* Ws  = sm + OFF_W;   // [96][396] W slice: rows = {r,z,n} x 32 j (tf32), stationary
    float* Cs  = sm + OFF_C;   // [4][32][36] staging: r, z, xn, hn
    float* Hs  = sm + OFF_H;   // [32][36] exact fp32 masked h(t-1), own j-slice
    float* bnx = sm + OFF_BN;  // [32] b_ih for n gate (added in fp32)
    float* dm  = sm + OFF_DM;  // [32] done mask (1-d), staged pre-spin

    const int tid = threadIdx.x;
    const int cta = blockIdx.x;
    const int sc  = cta / G_J;           // seq-chunk
    const int jc  = cta % G_J;           // j-chunk
    const int seq_base = sc * SEQ_TILE;
    const int j_base   = jc * J_TILE;

    // ---- one-time: load stationary W slice (tf32) ----
    for (int i = tid; i < 3*J_TILE*KPAD; i += NTHREADS) {
        int row = i / KPAD;
        int k   = i % KPAD;
        int g   = row / J_TILE;
        int jl  = row % J_TILE;
        int grow = g*HH + j_base + jl;
        float v;
        if (k < KX)        v = W_ih[(size_t)grow*FF + k];
        else if (k < KTOT) v = W_hh[(size_t)grow*HH + (k - KX)];
        else if (k == KTOT) v = (g < 2) ? (b_ih[grow] + b_hh[grow]) : b_hh[grow];
        else               v = 0.0f;
        Ws[row*KPAD + k] = wmma::__float_to_tf32(v);
    }
    if (tid < J_TILE) bnx[tid] = b_ih[2*HH + j_base + tid];
    // constant A columns: ones col (bias) + zero pad; data cols rewritten each step
    if (tid < SEQ_TILE) {
        As[tid*KPAD + KTOT] = wmma::__float_to_tf32(1.0f);
        #pragma unroll
        for (int k = KTOT+1; k < KPAD; ++k) As[tid*KPAD + k] = 0.0f;
    }
    __syncthreads();

    const int wid  = tid >> 5;
    const int ni   = wid & 1;     // n 16-block
    const int kh   = wid >> 1;    // k half
    const int k0   = kh ? 192 : 0;
    const int k1   = kh ? KEND : 192;

    const float* Wr = Ws + (0*J_TILE + ni*16)*KPAD;
    const float* Wz = Ws + (1*J_TILE + ni*16)*KPAD;
    const float* Wn = Ws + (2*J_TILE + ni*16)*KPAD;

    for (int t = 0; t < TT; ++t) {
        // ---- independent prework (overlaps the spin): x tile + done mask ----
        const float* xp = x + ((size_t)t*BNX + seq_base)*FF;
        for (int i = tid; i < SEQ_TILE*(FF/4); i += NTHREADS) {
            int s  = i / (FF/4);
            int c4 = i % (FF/4);
            float4 v = __ldg((const float4*)(xp + (size_t)s*FF) + c4);
            float4 w;
            w.x = wmma::__float_to_tf32(v.x);
            w.y = wmma::__float_to_tf32(v.y);
            w.z = wmma::__float_to_tf32(v.z);
            w.w = wmma::__float_to_tf32(v.w);
            *(float4*)(As + s*KPAD + c4*4) = w;
        }
        if (tid < SEQ_TILE)
            dm[tid] = __ldg(dones + (size_t)t*BNX + seq_base + tid) ? 0.0f : 1.0f;

        // ---- wait for peers' h(t-1); barrier also publishes dm/x-tile ----
        if (t > 0 && tid < G_J) {
            while (ld_flag(&g_flags[sc][tid]) < t) { __nanosleep(32); }
        }
        __syncthreads();

        // ---- fill A tile: masked h(t-1) (tf32); stash exact fp32 slice into Hs ----
        // All cross-CTA h reads use .cg (L2-only) -> never stale-L1; producer did
        // threadfence before its flag store, so L2 already holds h(t-1).
        const float* hp = (t == 0) ? (h0 + (size_t)seq_base*HH)
                                   : (out + ((size_t)(t-1)*BNX + seq_base)*HH);
        for (int i = tid; i < SEQ_TILE*(HH/4); i += NTHREADS) {
            int s  = i / (HH/4);
            int c4 = i % (HH/4);
            float4 v = __ldcg((const float4*)(hp + (size_t)s*HH) + c4);
            float m = dm[s];
            float4 e;                      // exact masked fp32
            e.x = v.x * m; e.y = v.y * m; e.z = v.z * m; e.w = v.w * m;
            int c = c4 * 4;                // global h column
            if (c >= j_base && c < j_base + J_TILE)
                *(float4*)(Hs + s*CLD + (c - j_base)) = e;
            float4 w;                      // tf32 for the MMA
            w.x = wmma::__float_to_tf32(e.x);
            w.y = wmma::__float_to_tf32(e.y);
            w.z = wmma::__float_to_tf32(e.z);
            w.w = wmma::__float_to_tf32(e.w);
            *(float4*)(As + s*KPAD + KX + c) = w;
        }
        __syncthreads();

        // ---- fused GEMM: [32 x 392] @ [96 x 392]^T, split-K across warp pairs ----
        FragC c_r[2], c_z[2], c_n[2], c_h[2];
        #pragma unroll
        for (int m = 0; m < 2; ++m) {
            wmma::fill_fragment(c_r[m], 0.0f);
            wmma::fill_fragment(c_z[m], 0.0f);
            wmma::fill_fragment(c_n[m], 0.0f);
            wmma::fill_fragment(c_h[m], 0.0f);
        }
        for (int kk = k0; kk < k1; kk += 8) {
            FragA a0, a1;
            wmma::load_matrix_sync(a0, As + 0*16*KPAD + kk, KPAD);
            wmma::load_matrix_sync(a1, As + 1*16*KPAD + kk, KPAD);
            FragB b;
            wmma::load_matrix_sync(b, Wr + kk, KPAD);
            wmma::mma_sync(c_r[0], a0, b, c_r[0]);
            wmma::mma_sync(c_r[1], a1, b, c_r[1]);
            wmma::load_matrix_sync(b, Wz + kk, KPAD);
            wmma::mma_sync(c_z[0], a0, b, c_z[0]);
            wmma::mma_sync(c_z[1], a1, b, c_z[1]);
            wmma::load_matrix_sync(b, Wn + kk, KPAD);
            if (kk < KX) {  // x phase -> xn
                wmma::mma_sync(c_n[0], a0, b, c_n[0]);
                wmma::mma_sync(c_n[1], a1, b, c_n[1]);
            } else {        // h phase -> hn (includes b_hh via ones col)
                wmma::mma_sync(c_h[0], a0, b, c_h[0]);
                wmma::mma_sync(c_h[1], a1, b, c_h[1]);
            }
        }

        // ---- split-K reduction via smem staging ----
        if (kh == 1) {
            #pragma unroll
            for (int m = 0; m < 2; ++m) {
                wmma::store_matrix_sync(Cs + 0*SEQ_TILE*CLD + m*16*CLD + ni*16, c_r[m], CLD, wmma::mem_row_major);
                wmma::store_matrix_sync(Cs + 1*SEQ_TILE*CLD + m*16*CLD + ni*16, c_z[m], CLD, wmma::mem_row_major);
                wmma::store_matrix_sync(Cs + 2*SEQ_TILE*CLD + m*16*CLD + ni*16, c_n[m], CLD, wmma::mem_row_major);
                wmma::store_matrix_sync(Cs + 3*SEQ_TILE*CLD + m*16*CLD + ni*16, c_h[m], CLD, wmma::mem_row_major);
            }
        }
        __syncthreads();
        if (kh == 0) {
            FragC tmp;
            #pragma unroll
            for (int m = 0; m < 2; ++m) {
                float* p;
                p = Cs + 0*SEQ_TILE*CLD + m*16*CLD + ni*16;
                wmma::load_matrix_sync(tmp, p, CLD, wmma::mem_row_major);
                for (int e = 0; e < tmp.num_elements; ++e) c_r[m].x[e] += tmp.x[e];
                wmma::store_matrix_sync(p, c_r[m], CLD, wmma::mem_row_major);
                p = Cs + 1*SEQ_TILE*CLD + m*16*CLD + ni*16;
                wmma::load_matrix_sync(tmp, p, CLD, wmma::mem_row_major);
                for (int e = 0; e < tmp.num_elements; ++e) c_z[m].x[e] += tmp.x[e];
                wmma::store_matrix_sync(p, c_z[m], CLD, wmma::mem_row_major);
                p = Cs + 2*SEQ_TILE*CLD + m*16*CLD + ni*16;
                wmma::load_matrix_sync(tmp, p, CLD, wmma::mem_row_major);
                for (int e = 0; e < tmp.num_elements; ++e) c_n[m].x[e] += tmp.x[e];
                wmma::store_matrix_sync(p, c_n[m], CLD, wmma::mem_row_major);
                p = Cs + 3*SEQ_TILE*CLD + m*16*CLD + ni*16;
                wmma::load_matrix_sync(tmp, p, CLD, wmma::mem_row_major);
                for (int e = 0; e < tmp.num_elements; ++e) c_h[m].x[e] += tmp.x[e];
                wmma::store_matrix_sync(p, c_h[m], CLD, wmma::mem_row_major);
            }
        }
        __syncthreads();

        // ---- gate math + write h(t) (stores via .cg: L2 is the coherence point) ----
        {
            int s  = tid >> 2;          // 0..31
            int j0 = (tid & 3) * 8;     // 0,8,16,24
            float r8[8];
            #pragma unroll
            for (int jj = 0; jj < 8; ++jj) {
                int j = j0 + jj;
                float cr = Cs[0*SEQ_TILE*CLD + s*CLD + j];
                float cz = Cs[1*SEQ_TILE*CLD + s*CLD + j];
                float cn = Cs[2*SEQ_TILE*CLD + s*CLD + j];
                float ch = Cs[3*SEQ_TILE*CLD + s*CLD + j];
                float r = sigf(cr);
                float z = sigf(cz);
                float n = tanhf(cn + bnx[j] + r * ch);
                float hprev = Hs[s*CLD + j];           // exact fp32 masked h(t-1)
                r8[jj] = (1.0f - z) * n + z * hprev;
            }
            float* op = out + ((size_t)t*BNX + seq_base + s)*HH + j_base + j0;
            __stcg((float4*)(op + 0), make_float4(r8[0], r8[1], r8[2], r8[3]));
            __stcg((float4*)(op + 4), make_float4(r8[4], r8[5], r8[6], r8[7]));
            if (t == TT-1) {
                float* fp = out + (size_t)TT*BNX*HH + (size_t)(seq_base + s)*HH + j_base + j0;
                __stcg((float4*)(fp + 0), make_float4(r8[0], r8[1], r8[2], r8[3]));
                __stcg((float4*)(fp + 4), make_float4(r8[4], r8[5], r8[6], r8[7]));
            }
        }

        // ---- publish step completion to the 8-CTA group (release: fence, then flag) ----
        __threadfence();
        __syncthreads();
        if (tid == 0) st_flag(&g_flags[sc][jc], t + 1);
    }
}

extern "C" void kernel_launch(void* const* d_in, const int* in_sizes, int n_in,
                              void* d_out, int out_size) {
    (void)in_sizes; (void)n_in; (void)out_size;
    const float* x     = (const float*)d_in[0];
    const int*   dones = (const int*)  d_in[1];
    const float* h0    = (const float*)d_in[2];
    const float* W_ih  = (const float*)d_in[3];
    const float* W_hh  = (const float*)d_in[4];
    const float* b_ih  = (const float*)d_in[5];
    const float* b_hh  = (const float*)d_in[6];
    float* out = (float*)d_out;

    cudaFuncSetAttribute(slotgru_persistent_kernel,
                         cudaFuncAttributeMaxDynamicSharedMemorySize, SMEM_BYTES);

    reset_flags_kernel<<<1, NCTA>>>();
    slotgru_persistent_kernel<<<NCTA, NTHREADS, SMEM_BYTES>>>(
        x, dones, h0, W_ih, W_hh, b_ih, b_hh, out);
}

// round 13
// speedup vs baseline: 1.1052x; 1.1052x over previous
#include <cuda_runtime.h>
#include <mma.h>
#include <cstdint>

using namespace nvcuda;

// Problem dims
#define TT   256
#define BB   32
#define NN   16
#define FF   128
#define HH   256
#define BNX  (BB*NN)        // 512 sequences
#define KX   FF             // 128 (x part of K)
#define KTOT (FF+HH)        // 384 (x | h); bias ones-col at 384
#define KEND (KTOT+8)       // 392: GEMM k upper bound (covers bias col)
#define KPAD 396            // row stride in floats (396 % 32 == 12 -> fewer LDS bank conflicts)

// Tiling
#define SEQ_TILE 32
#define J_TILE   32
#define G_SEQ (BNX/SEQ_TILE)   // 16 seq-chunks
#define G_J   (HH/J_TILE)      // 8 j-chunks
#define NCTA  (G_SEQ*G_J)      // 128 CTAs (1 per SM -> co-resident on 148 SMs)
#define NTHREADS 384           // 12 warps: one 16x16 output tile each, full K

// smem layout (floats)
#define OFF_A 0
#define SZ_A  (SEQ_TILE*KPAD)          // 12672
#define OFF_W (OFF_A + SZ_A)
#define SZ_W  (3*J_TILE*KPAD)          // 38016
#define OFF_C (OFF_W + SZ_W)
#define CLD   36
#define SZ_C  (4*SEQ_TILE*CLD)         // 4608 (r, z, xn, hn)
#define OFF_H (OFF_C + SZ_C)
#define SZ_H  (SEQ_TILE*CLD)           // 1152 (exact fp32 masked-h slice)
#define OFF_BN (OFF_H + SZ_H)          // 32 floats
#define OFF_DM (OFF_BN + J_TILE)       // 32 floats
#define SMEM_FLOATS (OFF_DM + SEQ_TILE)
#define SMEM_BYTES  (SMEM_FLOATS*4)    // 226,048 B < 232,448 B dynamic-smem cap

// Cross-CTA step flags (per seq-chunk group of 8 CTAs)
__device__ int g_flags[G_SEQ][G_J];

__global__ void reset_flags_kernel() {
    int i = threadIdx.x;
    if (i < NCTA) ((int*)g_flags)[i] = 0;
}

// Fast, saturation-correct activations (independent of fast-math flags)
__device__ __forceinline__ float sigf(float v) {
    return __fdividef(1.0f, 1.0f + __expf(-v));     // v<<0: exp->inf -> 0 ; v>>0 -> 1
}
__device__ __forceinline__ float tanhfast(float v) {
    float e = __expf(2.0f * v);                     // v>>0: inf -> 1 ; v<<0: 0 -> -1
    return 1.0f - __fdividef(2.0f, e + 1.0f);
}

// Guaranteed-reload L2 poll / L2 publish (avoid ATOMG RMW serialization)
__device__ __forceinline__ int ld_flag(const int* p) {
    int v; asm volatile("ld.global.cg.b32 %0, [%1];" : "=r"(v) : "l"(p) : "memory"); return v;
}
__device__ __forceinline__ void st_flag(int* p, int v) {
    asm volatile("st.global.cg.b32 [%0], %1;" :: "l"(p), "r"(v) : "memory");
}

typedef wmma::fragment<wmma::matrix_a, 16,16,8, wmma::precision::tf32, wmma::row_major> FragA;
typedef wmma::fragment<wmma::matrix_b, 16,16,8, wmma::precision::tf32, wmma::col_major> FragB;
typedef wmma::fragment<wmma::accumulator, 16,16,8, float> FragC;

__global__ void __launch_bounds__(NTHREADS, 1)
slotgru_persistent_kernel(const float* __restrict__ x,
                          const int*   __restrict__ dones,
                          const float* __restrict__ h0,
                          const float* __restrict__ W_ih,
                          const float* __restrict__ W_hh,
                          const float* __restrict__ b_ih,
                          const float* __restrict__ b_hh,
                          float* __restrict__ out)
{
    extern __shared__ float sm[];
    float* As  = sm + OFF_A;   // [32][396] A tile: [x_t | masked h | 1 | 0..] (tf32)
    float* Ws  = sm + OFF_W;   // [96][396] W slice: rows = {r,z,n} x 32 j (tf32), stationary
    float* Cs  = sm + OFF_C;   // [4][32][36] staging: r, z, xn, hn
    float* Hs  = sm + OFF_H;   // [32][36] exact fp32 masked h(t-1), own j-slice
    float* bnx = sm + OFF_BN;  // [32] b_ih for n gate (added in fp32)
    float* dm  = sm + OFF_DM;  // [32] done mask (1-d), staged pre-spin

    const int tid = threadIdx.x;
    const int cta = blockIdx.x;
    const int sc  = cta / G_J;           // seq-chunk
    const int jc  = cta % G_J;           // j-chunk
    const int seq_base = sc * SEQ_TILE;
    const int j_base   = jc * J_TILE;

    // ---- one-time: load stationary W slice (tf32) ----
    for (int i = tid; i < 3*J_TILE*KPAD; i += NTHREADS) {
        int row = i / KPAD;
        int k   = i % KPAD;
        int g   = row / J_TILE;
        int jl  = row % J_TILE;
        int grow = g*HH + j_base + jl;
        float v;
        if (k < KX)        v = W_ih[(size_t)grow*FF + k];
        else if (k < KTOT) v = W_hh[(size_t)grow*HH + (k - KX)];
        else if (k == KTOT) v = (g < 2) ? (b_ih[grow] + b_hh[grow]) : b_hh[grow];
        else               v = 0.0f;
        Ws[row*KPAD + k] = wmma::__float_to_tf32(v);
    }
    if (tid < J_TILE) bnx[tid] = b_ih[2*HH + j_base + tid];
    // constant A columns: ones col (bias) + zero pad; data cols rewritten each step
    if (tid < SEQ_TILE) {
        As[tid*KPAD + KTOT] = wmma::__float_to_tf32(1.0f);
        #pragma unroll
        for (int k = KTOT+1; k < KPAD; ++k) As[tid*KPAD + k] = 0.0f;
    }
    __syncthreads();

    // 12 warps -> 12 independent 16x16 output tiles (full K each, no split-K reduction)
    const int wid = tid >> 5;
    const int nt  = wid >> 1;              // n-tile 0..5 over 96 gate rows (r0 r1 z0 z1 n0 n1)
    const int mi  = wid & 1;               // m-tile 0..1 over 32 seqs
    const bool is_n = (nt >= 4);
    const float* Wb = Ws + nt*16*KPAD;     // this warp's B rows
    const float* Ab = As + mi*16*KPAD;     // this warp's A rows

    for (int t = 0; t < TT; ++t) {
        // ---- independent prework (no peer dependency): x tile + done mask ----
        const float* xp = x + ((size_t)t*BNX + seq_base)*FF;
        for (int i = tid; i < SEQ_TILE*(FF/4); i += NTHREADS) {
            int s  = i / (FF/4);
            int c4 = i % (FF/4);
            float4 v = __ldg((const float4*)(xp + (size_t)s*FF) + c4);
            float4 w;
            w.x = wmma::__float_to_tf32(v.x);
            w.y = wmma::__float_to_tf32(v.y);
            w.z = wmma::__float_to_tf32(v.z);
            w.w = wmma::__float_to_tf32(v.w);
            *(float4*)(As + s*KPAD + c4*4) = w;
        }
        if (tid < SEQ_TILE)
            dm[tid] = __ldg(dones + (size_t)t*BNX + seq_base + tid) ? 0.0f : 1.0f;
        __syncthreads();

        // ---- phase A GEMM (x columns, kk < 128) — overlaps the peer wait ----
        FragC acc0, acc1;
        wmma::fill_fragment(acc0, 0.0f);
        if (is_n) wmma::fill_fragment(acc1, 0.0f);
        #pragma unroll 4
        for (int kk = 0; kk < KX; kk += 8) {
            FragA a; FragB b;
            wmma::load_matrix_sync(a, Ab + kk, KPAD);
            wmma::load_matrix_sync(b, Wb + kk, KPAD);
            wmma::mma_sync(acc0, a, b, acc0);
        }

        // ---- wait for peers' h(t-1) ----
        if (t > 0 && tid < G_J) {
            while (ld_flag(&g_flags[sc][tid]) < t) { __nanosleep(32); }
        }
        __syncthreads();

        // ---- fill A tile: masked h(t-1) (tf32); stash exact fp32 slice into Hs ----
        // All cross-CTA h reads use .cg (L2-only) -> never stale-L1; producer did
        // a gpu-scope release before its flag store, so L2 already holds h(t-1).
        // (Writes cols >= KX only; phase-A readers touched cols < KX — disjoint.)
        const float* hp = (t == 0) ? (h0 + (size_t)seq_base*HH)
                                   : (out + ((size_t)(t-1)*BNX + seq_base)*HH);
        for (int i = tid; i < SEQ_TILE*(HH/4); i += NTHREADS) {
            int s  = i / (HH/4);
            int c4 = i % (HH/4);
            float4 v = __ldcg((const float4*)(hp + (size_t)s*HH) + c4);
            float m = dm[s];
            float4 e;                      // exact masked fp32
            e.x = v.x * m; e.y = v.y * m; e.z = v.z * m; e.w = v.w * m;
            int c = c4 * 4;                // global h column
            if (c >= j_base && c < j_base + J_TILE)
                *(float4*)(Hs + s*CLD + (c - j_base)) = e;
            float4 w;                      // tf32 for the MMA
            w.x = wmma::__float_to_tf32(e.x);
            w.y = wmma::__float_to_tf32(e.y);
            w.z = wmma::__float_to_tf32(e.z);
            w.w = wmma::__float_to_tf32(e.w);
            *(float4*)(As + s*KPAD + KX + c) = w;
        }
        __syncthreads();

        // ---- phase B GEMM (h columns + bias col, kk in [128, 392)) ----
        if (is_n) {
            #pragma unroll 4
            for (int kk = KX; kk < KEND; kk += 8) {
                FragA a; FragB b;
                wmma::load_matrix_sync(a, Ab + kk, KPAD);
                wmma::load_matrix_sync(b, Wb + kk, KPAD);
                wmma::mma_sync(acc1, a, b, acc1);   // hn (incl. b_hh via ones col)
            }
        } else {
            #pragma unroll 4
            for (int kk = KX; kk < KEND; kk += 8) {
                FragA a; FragB b;
                wmma::load_matrix_sync(a, Ab + kk, KPAD);
                wmma::load_matrix_sync(b, Wb + kk, KPAD);
                wmma::mma_sync(acc0, a, b, acc0);   // r/z full preact (incl. biases)
            }
        }

        // ---- stage results to Cs (single pass, no reduction needed) ----
        {
            int j16 = nt & 1;
            if (nt < 2) {        // r
                wmma::store_matrix_sync(Cs + 0*SEQ_TILE*CLD + mi*16*CLD + j16*16, acc0, CLD, wmma::mem_row_major);
            } else if (nt < 4) { // z
                wmma::store_matrix_sync(Cs + 1*SEQ_TILE*CLD + mi*16*CLD + j16*16, acc0, CLD, wmma::mem_row_major);
            } else {             // n: xn + hn
                wmma::store_matrix_sync(Cs + 2*SEQ_TILE*CLD + mi*16*CLD + j16*16, acc0, CLD, wmma::mem_row_major);
                wmma::store_matrix_sync(Cs + 3*SEQ_TILE*CLD + mi*16*CLD + j16*16, acc1, CLD, wmma::mem_row_major);
            }
        }
        __syncthreads();

        // ---- gate math + write h(t) (stores via .cg: L2 is the coherence point) ----
        if (tid < 256) {
            int s  = tid >> 3;          // 0..31
            int j0 = (tid & 7) * 4;     // 0,4,...,28
            float r4[4];
            #pragma unroll
            for (int jj = 0; jj < 4; ++jj) {
                int j = j0 + jj;
                float cr = Cs[0*SEQ_TILE*CLD + s*CLD + j];
                float cz = Cs[1*SEQ_TILE*CLD + s*CLD + j];
                float cn = Cs[2*SEQ_TILE*CLD + s*CLD + j];
                float ch = Cs[3*SEQ_TILE*CLD + s*CLD + j];
                float r = sigf(cr);
                float z = sigf(cz);
                float n = tanhfast(cn + bnx[j] + r * ch);
                float hprev = Hs[s*CLD + j];           // exact fp32 masked h(t-1)
                r4[jj] = (1.0f - z) * n + z * hprev;
            }
            float* op = out + ((size_t)t*BNX + seq_base + s)*HH + j_base + j0;
            __stcg((float4*)op, make_float4(r4[0], r4[1], r4[2], r4[3]));
            if (t == TT-1) {
                float* fp = out + (size_t)TT*BNX*HH + (size_t)(seq_base + s)*HH + j_base + j0;
                __stcg((float4*)fp, make_float4(r4[0], r4[1], r4[2], r4[3]));
            }
        }

        // ---- publish step completion to the 8-CTA group ----
        // bar.sync synchronizes-with all CTA threads' prior stores; a single
        // gpu-scope fence by tid 0 then orders them before the flag store
        // (standard grid-sync release pattern; avoids 12 warp-wide MEMBARs).
        __syncthreads();
        if (tid == 0) {
            asm volatile("fence.acq_rel.gpu;" ::: "memory");
            st_flag(&g_flags[sc][jc], t + 1);
        }
    }
}

extern "C" void kernel_launch(void* const* d_in, const int* in_sizes, int n_in,
                              void* d_out, int out_size) {
    (void)in_sizes; (void)n_in; (void)out_size;
    const float* x     = (const float*)d_in[0];
    const int*   dones = (const int*)  d_in[1];
    const float* h0    = (const float*)d_in[2];
    const float* W_ih  = (const float*)d_in[3];
    const float* W_hh  = (const float*)d_in[4];
    const float* b_ih  = (const float*)d_in[5];
    const float* b_hh  = (const float*)d_in[6];
    float* out = (float*)d_out;

    cudaFuncSetAttribute(slotgru_persistent_kernel,
                         cudaFuncAttributeMaxDynamicSharedMemorySize, SMEM_BYTES);

    reset_flags_kernel<<<1, NCTA>>>();
    slotgru_persistent_kernel<<<NCTA, NTHREADS, SMEM_BYTES>>>(
        x, dones, h0, W_ih, W_hh, b_ih, b_hh, out);
}